// round 16
// baseline (speedup 1.0000x reference)
#include <cuda_runtime.h>
#include <cuda_fp16.h>
#include <cuda_bf16.h>
#include <cstdint>

#define N_NODESC 100000
#define N_EDGESC 1600000
#define N_GRAPHS 2048
#define VOCABC   1000
#define HID      64
#define N_CL     2
#define SCAN_B   1024
#define NB_N     ((N_NODESC + SCAN_B - 1) / SCAN_B)   // 98
#define NB_G     ((N_GRAPHS + SCAN_B - 1) / SCAN_B)   // 2
#define VB       ((VOCABC + 7) / 8)                   // vocab blocks (8 rows/block)
#define POOL_G   1184
// dynamic smem layout for k_gather_mm
#define TV_BYTES (VOCABC * HID * 2)                   // 128000
#define SW_BYTES (HID * HID * 4)                      // 16384
#define SE_BYTES (32 * 32 * 16)                       // 16384
#define MM_SMEM  (TV_BYTES + SW_BYTES + SE_BYTES)     // 160768

// ---------------- scratch (device globals; referenced ONLY from device code) -
__device__ int            g_degi[N_NODESC];
__device__ int            g_incl[N_NODESC];    // inclusive scan of deg (CSR row ends)
__device__ int            g_cursor[N_NODESC];  // exclusive prefix (read-only in fill)
__device__ unsigned short g_rank[N_EDGESC];    // edge rank within its target group
__device__ int            g_gcnt[N_GRAPHS];
__device__ int            g_gincl[N_GRAPHS];
__device__ int            g_bsum[NB_N + NB_G];
__device__ int            g_arrive;
__device__ int            g_arrive2;
__device__ float          g_dinv[N_NODESC];
__device__ unsigned int   g_px[N_NODESC];      // packed (x:u16 | dinv-fp16 << 16)
__device__ unsigned int   g_csr[N_EDGESC];     // packed (x[src], dinv[src]) per slot
__device__ int            g_csr_id[N_EDGESC];  // source node id per slot (layer 2)
__device__ __half         g_tvh[VOCABC * HID]; // emb @ W1, fp16, natural col order
__device__ __half         g_ts2[(size_t)N_NODESC * HID];  // layer-2 messages (fp16)
__device__ float          g_sums[(size_t)N_GRAPHS * HID]; // pooled sums

// ---------------- zero scratch ----------------------------------------------
__global__ void k_zero(int N) {
    int i = blockIdx.x * blockDim.x + threadIdx.x;
    if (i < N) g_degi[i] = 0;
    if (i < N_GRAPHS) g_gcnt[i] = 0;
    if (i < N_GRAPHS * HID) g_sums[i] = 0.f;
    if (i == 0) { g_arrive = 0; g_arrive2 = 0; }
}

// ---------------- fused: counts (+edge ranks) + vocab GEMM (fp16 out) --------
__global__ void k_count_vocab(const int* __restrict__ col,
                              const int* __restrict__ batch,
                              const float* __restrict__ emb,
                              const float* __restrict__ W, int E, int N, int V) {
    __shared__ float sW[HID * HID];
    if (blockIdx.x < VB) {
        int tid = threadIdx.x;
        for (int i = tid; i < HID * HID; i += blockDim.x) sW[i] = W[i];
        __syncthreads();
        int lane = tid & 31, warp = tid >> 5;
        int r = blockIdx.x * 8 + warp;
        if (r >= V) return;
        const float* e = emb + (size_t)r * HID;
        float e_lo = e[lane], e_hi = e[lane + 32];
        // lane owns columns 2*lane, 2*lane+1 (natural order for half2 rows)
        float a0 = 0.f, a1 = 0.f;
        #pragma unroll
        for (int k = 0; k < 32; k++) {
            float ek = __shfl_sync(0xffffffffu, e_lo, k);
            a0 = fmaf(ek, sW[k * HID + 2 * lane],     a0);
            a1 = fmaf(ek, sW[k * HID + 2 * lane + 1], a1);
        }
        #pragma unroll
        for (int k = 0; k < 32; k++) {
            float ek = __shfl_sync(0xffffffffu, e_hi, k);
            a0 = fmaf(ek, sW[(k + 32) * HID + 2 * lane],     a0);
            a1 = fmaf(ek, sW[(k + 32) * HID + 2 * lane + 1], a1);
        }
        reinterpret_cast<__half2*>(g_tvh)[(size_t)r * 32 + lane] =
            __floats2half2_rn(a0, a1);
    } else {
        int i = (blockIdx.x - VB) * blockDim.x + threadIdx.x;
        if (i < E) {
            int r = atomicAdd(&g_degi[col[i]], 1);
            g_rank[i] = (unsigned short)r;
        } else if (i < E + N) {
            atomicAdd(&g_gcnt[batch[i - E]], 1);
        }
    }
}

// ---------------- one-launch dual scan + px build ----------------------------
__device__ __forceinline__ int warp_incl_scan(int x, int lane) {
    #pragma unroll
    for (int o = 1; o < 32; o <<= 1) {
        int u = __shfl_up_sync(0xffffffffu, x, o);
        if (lane >= o) x += u;
    }
    return x;
}

__global__ void k_scan_all(const int* __restrict__ xarr, int N) {
    __shared__ int wsum[32];
    __shared__ int spre;
    int t = threadIdx.x, lane = t & 31, w = t >> 5;
    bool isDeg = blockIdx.x < NB_N;
    int lo  = isDeg ? 0 : NB_N;
    int n   = isDeg ? N : N_GRAPHS;
    int idx = (blockIdx.x - lo) * SCAN_B + t;
    int v   = 0;
    if (idx < n) v = isDeg ? g_degi[idx] : g_gcnt[idx];

    int incl = warp_incl_scan(v, lane);
    if (lane == 31) wsum[w] = incl;
    __syncthreads();
    if (w == 0) wsum[lane] = warp_incl_scan(wsum[lane], lane);
    __syncthreads();
    int blockIncl = incl + (w > 0 ? wsum[w - 1] : 0);
    int blockTot = wsum[31];

    if (t == 0) {
        g_bsum[blockIdx.x] = blockTot;
        __threadfence();
        atomicAdd(&g_arrive, 1);
        while (atomicAdd(&g_arrive, 0) < (int)gridDim.x) { }
    }
    __syncthreads();

    if (w == 0) {
        int pre = 0;
        for (int j = lo + lane; j < (int)blockIdx.x; j += 32) pre += g_bsum[j];
        #pragma unroll
        for (int o = 16; o > 0; o >>= 1) pre += __shfl_down_sync(0xffffffffu, pre, o);
        if (lane == 0) spre = pre;
    }
    __syncthreads();
    int fin = blockIncl + spre;

    if (idx < n) {
        if (isDeg) {
            float dv = rsqrtf((float)(v + 1));       // +1 self loop
            g_incl[idx]   = fin;
            g_cursor[idx] = fin - v;                 // exclusive prefix
            g_dinv[idx]   = dv;
            unsigned int xv = (unsigned int)xarr[idx] & 0xFFFFu;
            unsigned short dh = __half_as_ushort(__float2half_rn(dv));
            g_px[idx] = xv | ((unsigned int)dh << 16);
        } else {
            g_gincl[idx] = fin;
        }
    }
}

// ---------------- CSR fill: packed (x,dinv) entry + source id, one pass ------
__global__ void k_fill(const int* __restrict__ row,
                       const int* __restrict__ col, int E) {
    int i = blockIdx.x * blockDim.x + threadIdx.x;
    if (i >= E) return;
    int c = col[i];
    int r = row[i];
    int slot = g_cursor[c] + (int)g_rank[i];
    g_csr[slot]    = g_px[r];        // for layer-1 smem-table gather
    g_csr_id[slot] = r;              // for layer-2 message gather
}

// ---------------- fused: layer-1 smem-table gather + ReLU + GEMM(W2) ---------
// One 1024-thread block per SM; vocab table (fp16, 128 KB) + W2 in smem.
__global__ void __launch_bounds__(1024, 1)
k_gather_mm(const float* __restrict__ b1,
            const float* __restrict__ W2, int n) {
    extern __shared__ char dyn[];
    __half2* stv = reinterpret_cast<__half2*>(dyn);                 // VOCAB*32
    float*   sW  = reinterpret_cast<float*>(dyn + TV_BYTES);        // 64*64
    float4*  se  = reinterpret_cast<float4*>(dyn + TV_BYTES + SW_BYTES); // 32*32

    int tid = threadIdx.x;
    const __half2* tvg = reinterpret_cast<const __half2*>(g_tvh);
    for (int i = tid; i < VOCABC * 32; i += blockDim.x) stv[i] = tvg[i];
    for (int i = tid; i < HID * HID; i += blockDim.x) sW[i] = W2[i];
    __syncthreads();

    int lane = tid & 31, warp = tid >> 5, wpb = blockDim.x >> 5;
    float2 bb = reinterpret_cast<const float2*>(b1)[lane];
    const unsigned long long* wu = reinterpret_cast<const unsigned long long*>(sW);
    const ulonglong2* eu = reinterpret_cast<const ulonglong2*>(&se[warp * 32]);

    for (int c = blockIdx.x * wpb + warp; c < n; c += gridDim.x * wpb) {
        // self message
        unsigned int pc = g_px[c];
        float2 acc;
        {
            float dd = __half2float(__ushort_as_half((unsigned short)(pc >> 16)));
            float2 f = __half22float2(stv[(pc & 0xFFFFu) * 32 + lane]);
            acc.x = dd * f.x;
            acc.y = dd * f.y;
        }
        int start = (c == 0) ? 0 : g_incl[c - 1];
        int end = g_incl[c];
        int e = start;
        while (e + 8 <= end) {
            unsigned int pk[8];
            #pragma unroll
            for (int j = 0; j < 8; j++) pk[j] = g_csr[e + j];   // broadcast loads
            float2 v[8];
            #pragma unroll
            for (int j = 0; j < 8; j++)
                v[j] = __half22float2(stv[(pk[j] & 0xFFFFu) * 32 + lane]);
            #pragma unroll
            for (int j = 0; j < 8; j++) {
                float dd = __half2float(__ushort_as_half((unsigned short)(pk[j] >> 16)));
                acc.x = fmaf(dd, v[j].x, acc.x);
                acc.y = fmaf(dd, v[j].y, acc.y);
            }
            e += 8;
        }
        for (; e < end; e++) {
            unsigned int pk = g_csr[e];
            float dd = __half2float(__ushort_as_half((unsigned short)(pk >> 16)));
            float2 f = __half22float2(stv[(pk & 0xFFFFu) * 32 + lane]);
            acc.x = fmaf(dd, f.x, acc.x);
            acc.y = fmaf(dd, f.y, acc.y);
        }
        float d = g_dinv[c];
        float ex = fmaxf(fmaf(d, acc.x, bb.x), 0.f);   // relu(h), col 2*lane
        float ey = fmaxf(fmaf(d, acc.y, bb.y), 0.f);   // col 2*lane+1
        __syncwarp();
        se[warp * 32 + lane] = make_float4(ex, ex, ey, ey);
        __syncwarp();
        unsigned long long gacc = 0ull;                // packed (0.f, 0.f)
        #pragma unroll
        for (int k = 0; k < HID; k += 2) {
            ulonglong2 ee = eu[k >> 1];                // dup(e_k), dup(e_{k+1})
            unsigned long long w0 = wu[k * 32 + lane];
            unsigned long long w1 = wu[(k + 1) * 32 + lane];
            asm("fma.rn.f32x2 %0, %1, %2, %0;" : "+l"(gacc) : "l"(ee.x), "l"(w0));
            asm("fma.rn.f32x2 %0, %1, %2, %0;" : "+l"(gacc) : "l"(ee.y), "l"(w1));
        }
        float a, bc;
        asm("mov.b64 {%0, %1}, %2;" : "=f"(a), "=f"(bc) : "l"(gacc));
        reinterpret_cast<__half2*>(g_ts2)[(size_t)c * 32 + lane] =
            __floats2half2_rn(a * d, bc * d);
    }
}

// ---------------- layer-2 gather + pool + fused head (persistent wave) -------
__global__ void k_gather_pool(const int* __restrict__ batch,
                              const float* __restrict__ b2,
                              const float* __restrict__ Wl,
                              const float* __restrict__ bl,
                              float* __restrict__ out, int n) {
    int lane = threadIdx.x & 31;
    int warp = threadIdx.x >> 5;
    int wpb = blockDim.x >> 5;
    const __half2* ts = reinterpret_cast<const __half2*>(g_ts2);
    for (int c = blockIdx.x * wpb + warp; c < n; c += gridDim.x * wpb) {
        int start = (c == 0) ? 0 : g_incl[c - 1];
        int end = g_incl[c];
        float2 a0 = __half22float2(ts[(size_t)c * 32 + lane]);
        float2 a1 = make_float2(0.f, 0.f);
        int e = start;
        while (e + 8 <= end) {
            int r[8];
            #pragma unroll
            for (int j = 0; j < 8; j++) r[j] = g_csr_id[e + j];
            float2 v[8];
            #pragma unroll
            for (int j = 0; j < 8; j++) v[j] = __half22float2(ts[(size_t)r[j] * 32 + lane]);
            #pragma unroll
            for (int j = 0; j < 8; j += 2) {
                a0.x += v[j].x;     a0.y += v[j].y;
                a1.x += v[j + 1].x; a1.y += v[j + 1].y;
            }
            e += 8;
        }
        if (e + 4 <= end) {
            int r[4];
            #pragma unroll
            for (int j = 0; j < 4; j++) r[j] = g_csr_id[e + j];
            float2 v[4];
            #pragma unroll
            for (int j = 0; j < 4; j++) v[j] = __half22float2(ts[(size_t)r[j] * 32 + lane]);
            a0.x += v[0].x + v[2].x; a0.y += v[0].y + v[2].y;
            a1.x += v[1].x + v[3].x; a1.y += v[1].y + v[3].y;
            e += 4;
        }
        for (; e < end; e++) {
            int r = g_csr_id[e];
            float2 v = __half22float2(ts[(size_t)r * 32 + lane]);
            a0.x += v.x; a0.y += v.y;
        }
        a0.x += a1.x;
        a0.y += a1.y;
        float d = g_dinv[c];
        float2 bb = reinterpret_cast<const float2*>(b2)[lane];
        float hx = fmaxf(fmaf(d, a0.x, bb.x), 0.f);
        float hy = fmaxf(fmaf(d, a0.y, bb.y), 0.f);
        int g = batch[c];
        float* dst = g_sums + (size_t)g * HID + 2 * lane;
        asm volatile("red.global.add.v2.f32 [%0], {%1,%2};"
                     :: "l"(dst), "f"(hx), "f"(hy) : "memory");
    }

    // ---- grid-wide arrive, then fused head (single persistent wave) ----
    __threadfence();
    __syncthreads();
    if (threadIdx.x == 0) {
        atomicAdd(&g_arrive2, 1);
        while (atomicAdd(&g_arrive2, 0) < (int)gridDim.x) { }
    }
    __syncthreads();

    int g = blockIdx.x * wpb + warp;
    if (g >= N_GRAPHS) return;
    int start = (g == 0) ? 0 : g_gincl[g - 1];
    int cnt = g_gincl[g] - start;
    float inv = 1.0f / fmaxf((float)cnt, 1.0f);
    float s0 = g_sums[(size_t)g * HID + 2 * lane] * inv;
    float s1 = g_sums[(size_t)g * HID + 2 * lane + 1] * inv;
    float a0 = s0 * Wl[(2 * lane) * N_CL + 0] + s1 * Wl[(2 * lane + 1) * N_CL + 0];
    float a1 = s0 * Wl[(2 * lane) * N_CL + 1] + s1 * Wl[(2 * lane + 1) * N_CL + 1];
    #pragma unroll
    for (int off = 16; off > 0; off >>= 1) {
        a0 += __shfl_down_sync(0xffffffffu, a0, off);
        a1 += __shfl_down_sync(0xffffffffu, a1, off);
    }
    if (lane == 0) {
        out[g * N_CL + 0] = a0 + bl[0];
        out[g * N_CL + 1] = a1 + bl[1];
    }
}

// ---------------- launch ----------------------------------------------------
extern "C" void kernel_launch(void* const* d_in, const int* in_sizes, int n_in,
                              void* d_out, int out_size) {
    const int*   x     = (const int*)  d_in[0];
    const int*   eidx  = (const int*)  d_in[1];
    const int*   batch = (const int*)  d_in[2];
    const float* emb   = (const float*)d_in[3];
    const float* W1    = (const float*)d_in[4];
    const float* b1    = (const float*)d_in[5];
    const float* W2    = (const float*)d_in[6];
    const float* b2    = (const float*)d_in[7];
    const float* Wl    = (const float*)d_in[8];
    const float* bl    = (const float*)d_in[9];
    float* out = (float*)d_out;

    const int N = in_sizes[0];
    const int E = in_sizes[1] / 2;
    const int V = in_sizes[3] / HID;
    const int* row = eidx;       // sources
    const int* col = eidx + E;   // targets

    const int T = 256;
    const int ZB = (N_GRAPHS * HID + T - 1) / T;
    const int CB = (E + N + T - 1) / T;

    static int smem_set = 0;
    if (!smem_set) {
        cudaFuncSetAttribute(k_gather_mm,
                             cudaFuncAttributeMaxDynamicSharedMemorySize, MM_SMEM);
        smem_set = 1;
    }

    // zero -> fused count+vocab GEMM -> dual scan (+px) -> CSR fill (one pass)
    k_zero       <<<ZB, T>>>(N);
    k_count_vocab<<<VB + CB, T>>>(col, batch, emb, W1, E, N, V);
    k_scan_all   <<<NB_N + NB_G, SCAN_B>>>(x, N);
    k_fill       <<<(E + T - 1) / T, T>>>(row, col, E);

    // layer 1: smem vocab-table gather + GEMM(W2) -> ts2 (148 big blocks)
    k_gather_mm<<<148, 1024, MM_SMEM>>>(b1, W2, N);

    // layer 2 gather + pool + head (single persistent wave)
    k_gather_pool<<<POOL_G, 256>>>(batch, b2, Wl, bl, out, N);
}